// round 4
// baseline (speedup 1.0000x reference)
#include <cuda_runtime.h>
#include <math.h>

#define CHUNK 512            // rows of t per block
// per-block partials: B * (S/CHUNK) = 128 * 8 = 1024 slots
__device__ double2 g_part[4096];

// ---------------------------------------------------------------------------
// Fused kernel: per (batch, chunk) block.
//  Phase 1: stream x rows, t[s] = w2·relu(w1·x+b1)+b2 into shared (+2 halo).
//  Phase 2: partial sum / sumsq of log|t[j+2]-t[j]| -> one double2 per block.
// Stat compute hides entirely under the 268 MB HBM stream.
// ---------------------------------------------------------------------------
__global__ __launch_bounds__(256)
void k_main(const float* __restrict__ x,
            const float* __restrict__ w1,
            const float* __restrict__ b1,
            const float* __restrict__ w2,
            const float* __restrict__ b2,
            int S, int C)
{
    __shared__ float  t_sh[CHUNK + 2];
    __shared__ double sh_s[8], sh_ss[8];

    const int b  = blockIdx.x / C;
    const int c  = blockIdx.x % C;
    const int s0 = c * CHUNK;
    const int nrows = min(CHUNK + 2, S - s0);   // +2 halo except at tail

    const int tid  = threadIdx.x;
    const int lane = tid & 31;
    const int wid  = tid >> 5;

    // lane-local weight slices (w1 is (2,128))
    const float4 a0 = reinterpret_cast<const float4*>(w1)[lane];
    const float4 a1 = reinterpret_cast<const float4*>(w1 + 128)[lane];
    const float bb0 = b1[0], bb1 = b1[1];
    const float c0 = w2[0], c1 = w2[1], cb = b2[0];

    const float4* __restrict__ X =
        reinterpret_cast<const float4*>(x) + ((size_t)b * S + s0) * 32;

    // Phase 1: 8 warps, 4 rows per warp-iteration (stride 32 rows)
    for (int r = wid * 4; r < nrows; r += 32) {
        const int nr = min(4, nrows - r);
        float4 v[4];
        #pragma unroll
        for (int j = 0; j < 4; ++j)
            if (j < nr) v[j] = X[(size_t)(r + j) * 32 + lane];

        float d0[4], d1[4];
        #pragma unroll
        for (int j = 0; j < 4; ++j) {
            d0[j] = v[j].x*a0.x + v[j].y*a0.y + v[j].z*a0.z + v[j].w*a0.w;
            d1[j] = v[j].x*a1.x + v[j].y*a1.y + v[j].z*a1.z + v[j].w*a1.w;
        }
        #pragma unroll
        for (int off = 16; off; off >>= 1) {
            #pragma unroll
            for (int j = 0; j < 4; ++j) {
                d0[j] += __shfl_xor_sync(0xffffffffu, d0[j], off);
                d1[j] += __shfl_xor_sync(0xffffffffu, d1[j], off);
            }
        }
        if (lane == 0) {
            #pragma unroll
            for (int j = 0; j < 4; ++j)
                if (j < nr) {
                    float h0 = fmaxf(d0[j] + bb0, 0.0f);
                    float h1 = fmaxf(d1[j] + bb1, 0.0f);
                    t_sh[r + j] = fmaf(c1, h1, fmaf(c0, h0, cb));
                }
        }
    }
    __syncthreads();

    // Phase 2: local log-diff stats (global i = s0+j valid while i < S-2)
    const int jmax = min(CHUNK, S - 2 - s0);
    double s = 0.0, ss = 0.0;
    for (int j = tid; j < jmax; j += 256) {
        float d = fabsf(t_sh[j + 2] - t_sh[j]);
        float l = logf(d + 1e-6f);
        s  += (double)l;
        ss += (double)l * (double)l;
    }
    #pragma unroll
    for (int off = 16; off; off >>= 1) {
        s  += __shfl_xor_sync(0xffffffffu, s,  off);
        ss += __shfl_xor_sync(0xffffffffu, ss, off);
    }
    if (lane == 0) { sh_s[wid] = s; sh_ss[wid] = ss; }
    __syncthreads();
    if (wid == 0) {
        double ts  = (lane < 8) ? sh_s[lane]  : 0.0;
        double tss = (lane < 8) ? sh_ss[lane] : 0.0;
        #pragma unroll
        for (int off = 4; off; off >>= 1) {
            ts  += __shfl_xor_sync(0xffffffffu, ts,  off);
            tss += __shfl_xor_sync(0xffffffffu, tss, off);
        }
        if (lane == 0) g_part[blockIdx.x] = make_double2(ts, tss);
    }
}

// ---------------------------------------------------------------------------
// Final: reduce C partials per batch, stats, tanh head, broadcast output.
// ---------------------------------------------------------------------------
__global__ __launch_bounds__(256)
void k_final(const float* __restrict__ w3,
             const float* __restrict__ b3,
             float* __restrict__ out,
             int S, int C, int dout)
{
    const int b   = blockIdx.x;
    const int tid = threadIdx.x;
    __shared__ alignas(16) float sh_stats[2];
    __shared__ alignas(16) float sh_o[64];

    if (tid < 32) {
        double s = 0.0, ss = 0.0;
        if (tid < C) { double2 p = g_part[b * C + tid]; s = p.x; ss = p.y; }
        #pragma unroll
        for (int off = 16; off; off >>= 1) {
            s  += __shfl_xor_sync(0xffffffffu, s,  off);
            ss += __shfl_xor_sync(0xffffffffu, ss, off);
        }
        if (tid == 0) {
            const double N = (double)(S - 2);
            double mean = s / N;
            double var  = (ss - s * s / N) / (N - 1.0);
            if (var < 0.0) var = 0.0;
            sh_stats[0] = (float)mean;
            sh_stats[1] = (float)sqrt(var);
        }
    }
    __syncthreads();

    if (tid < dout)
        sh_o[tid] = tanhf(sh_stats[0] * w3[2*tid] + sh_stats[1] * w3[2*tid + 1] + b3[tid]);
    __syncthreads();

    float4* __restrict__ ob = reinterpret_cast<float4*>(out + (size_t)b * dout * dout);
    const float4* __restrict__ so = reinterpret_cast<const float4*>(sh_o);
    const int total4 = (dout * dout) >> 2;     // 1024
    const int row4   = dout >> 2;              // 16
    for (int k = tid; k < total4; k += blockDim.x)
        ob[k] = so[k & (row4 - 1)];
}

extern "C" void kernel_launch(void* const* d_in, const int* in_sizes, int n_in,
                              void* d_out, int out_size)
{
    const float* x  = (const float*)d_in[0];
    const float* w1 = (const float*)d_in[1];
    const float* b1 = (const float*)d_in[2];
    const float* w2 = (const float*)d_in[3];
    const float* b2 = (const float*)d_in[4];
    const float* w3 = (const float*)d_in[5];
    const float* b3 = (const float*)d_in[6];
    float* out = (float*)d_out;

    const int DOUT = 64;
    const int B    = out_size / (DOUT * DOUT);    // 128
    const int rows = in_sizes[0] / 128;           // B * S
    const int S    = rows / B;                    // 4096
    const int C    = (S + CHUNK - 1) / CHUNK;     // 8 chunks per batch

    k_main<<<B * C, 256>>>(x, w1, b1, w2, b2, S, C);
    k_final<<<B, 256>>>(w3, b3, out, S, C, DOUT);
}

// round 5
// speedup vs baseline: 1.4867x; 1.4867x over previous
#include <cuda_runtime.h>
#include <math.h>

// Scratch: t[b,s] (B=128, S=4096)
__device__ float g_t[128 * 4096];

// ---------------------------------------------------------------------------
// Kernel 1 (UNCHANGED from R3 — measured 45.5us, DRAM 76%, streaming ceiling):
// t[b,s] = w2·relu(w1·x + b1) + b2, quad-per-row mapping.
// ---------------------------------------------------------------------------
__global__ __launch_bounds__(256, 2)
void k_transform(const float* __restrict__ x,
                 const float* __restrict__ w1,
                 const float* __restrict__ b1,
                 const float* __restrict__ w2,
                 const float* __restrict__ b2,
                 int rows)
{
    const int lane = threadIdx.x & 31;
    const int q    = lane & 3;
    const int sub  = lane >> 2;
    const int gwarp  = blockIdx.x * (blockDim.x >> 5) + (threadIdx.x >> 5);
    const int nwarps = gridDim.x * (blockDim.x >> 5);

    const float4* __restrict__ X = reinterpret_cast<const float4*>(x);
    const float4* __restrict__ W = reinterpret_cast<const float4*>(w1);

    float4 wa0[8], wa1[8];
    #pragma unroll
    for (int k = 0; k < 8; ++k) { wa0[k] = W[q + 4*k]; wa1[k] = W[32 + q + 4*k]; }
    const float bb0 = b1[0], bb1 = b1[1];
    const float c0 = w2[0], c1 = w2[1], cb = b2[0];

    const int octets = rows >> 3;
    for (int o = gwarp; o < octets; o += nwarps) {
        const int row = (o << 3) + sub;
        const size_t base = (size_t)row * 32 + q;

        float4 v[8];
        #pragma unroll
        for (int k = 0; k < 8; ++k) v[k] = X[base + 4*k];

        float d0 = 0.f, d1 = 0.f;
        #pragma unroll
        for (int k = 0; k < 8; ++k) {
            d0 += v[k].x*wa0[k].x + v[k].y*wa0[k].y + v[k].z*wa0[k].z + v[k].w*wa0[k].w;
            d1 += v[k].x*wa1[k].x + v[k].y*wa1[k].y + v[k].z*wa1[k].z + v[k].w*wa1[k].w;
        }
        d0 += __shfl_xor_sync(0xffffffffu, d0, 1);
        d0 += __shfl_xor_sync(0xffffffffu, d0, 2);
        d1 += __shfl_xor_sync(0xffffffffu, d1, 1);
        d1 += __shfl_xor_sync(0xffffffffu, d1, 2);

        if (q == 0) {
            float h0 = fmaxf(d0 + bb0, 0.0f);
            float h1 = fmaxf(d1 + bb1, 0.0f);
            g_t[row] = fmaf(c1, h1, fmaf(c0, h0, cb));
        }
    }
}

// ---------------------------------------------------------------------------
// Kernel 2: one block per batch does EVERYTHING downstream.
//  - float4 bulk copy of the 16KB t-row into shared (L2-resident after K1)
//  - 8 log-diffs/thread from shared; float partials -> double block reduction
//  - tanh head + broadcast write of this batch's 16KB output slice
// ---------------------------------------------------------------------------
__global__ __launch_bounds__(512)
void k_stats(const float* __restrict__ w3,
             const float* __restrict__ b3,
             float* __restrict__ out,
             int S, int dout)
{
    __shared__ alignas(16) float  t_sh[4096 + 4];
    __shared__ double sh_s[16], sh_ss[16];
    __shared__ alignas(16) float sh_stats[2];
    __shared__ alignas(16) float sh_o[64];

    const int b    = blockIdx.x;
    const int tid  = threadIdx.x;
    const int lane = tid & 31;
    const int wid  = tid >> 5;
    const int nthr = blockDim.x;

    // Phase A: coalesced float4 copy of t row into shared
    const float4* __restrict__ T4 = reinterpret_cast<const float4*>(g_t + (size_t)b * S);
    float4* __restrict__ S4 = reinterpret_cast<float4*>(t_sh);
    for (int k = tid; k < (S >> 2); k += nthr) S4[k] = T4[k];
    __syncthreads();

    // Phase B: log-diff partials (float per-thread, 8 terms each)
    const int N = S - 2;
    float fs = 0.f, fss = 0.f;
    for (int i = tid; i < N; i += nthr) {
        float d = fabsf(t_sh[i + 2] - t_sh[i]);
        float l = logf(d + 1e-6f);
        fs  += l;
        fss = fmaf(l, l, fss);
    }
    double s = (double)fs, ss = (double)fss;
    #pragma unroll
    for (int off = 16; off; off >>= 1) {
        s  += __shfl_xor_sync(0xffffffffu, s,  off);
        ss += __shfl_xor_sync(0xffffffffu, ss, off);
    }
    if (lane == 0) { sh_s[wid] = s; sh_ss[wid] = ss; }
    __syncthreads();
    if (wid == 0) {
        double ts  = (lane < 16) ? sh_s[lane]  : 0.0;
        double tss = (lane < 16) ? sh_ss[lane] : 0.0;
        #pragma unroll
        for (int off = 8; off; off >>= 1) {
            ts  += __shfl_xor_sync(0xffffffffu, ts,  off);
            tss += __shfl_xor_sync(0xffffffffu, tss, off);
        }
        if (lane == 0) {
            const double Nd = (double)N;
            double mean = ts / Nd;
            double var  = (tss - ts * ts / Nd) / (Nd - 1.0);
            if (var < 0.0) var = 0.0;
            sh_stats[0] = (float)mean;
            sh_stats[1] = (float)sqrt(var);
        }
    }
    __syncthreads();

    // Phase C: head + broadcast output (dout x dout identical rows)
    if (tid < dout)
        sh_o[tid] = tanhf(sh_stats[0] * w3[2*tid] + sh_stats[1] * w3[2*tid + 1] + b3[tid]);
    __syncthreads();

    float4* __restrict__ ob = reinterpret_cast<float4*>(out + (size_t)b * dout * dout);
    const float4* __restrict__ so = reinterpret_cast<const float4*>(sh_o);
    const int total4 = (dout * dout) >> 2;   // 1024
    const int row4   = dout >> 2;            // 16
    for (int k = tid; k < total4; k += nthr)
        ob[k] = so[k & (row4 - 1)];
}

extern "C" void kernel_launch(void* const* d_in, const int* in_sizes, int n_in,
                              void* d_out, int out_size)
{
    const float* x  = (const float*)d_in[0];
    const float* w1 = (const float*)d_in[1];
    const float* b1 = (const float*)d_in[2];
    const float* w2 = (const float*)d_in[3];
    const float* b2 = (const float*)d_in[4];
    const float* w3 = (const float*)d_in[5];
    const float* b3 = (const float*)d_in[6];
    float* out = (float*)d_out;

    const int DOUT = 64;
    const int B    = out_size / (DOUT * DOUT);   // 128
    const int rows = in_sizes[0] / 128;          // B * S
    const int S    = rows / B;                   // 4096

    k_transform<<<296, 256>>>(x, w1, b1, w2, b2, rows);
    k_stats<<<B, 512>>>(w3, b3, out, S, DOUT);
}